// round 1
// baseline (speedup 1.0000x reference)
#include <cuda_runtime.h>
#include <cuda_bf16.h>
#include <cstdint>

// ---------------------------------------------------------------------------
// Swin block: B=8, H=W=64, C=512, HEADS=16, dh=32, WS=8, SHIFT=4, N=64,
// nWin=64/batch -> 512 windows total, tokens T = 32768, MLP_DIM=2048.
// ---------------------------------------------------------------------------

#define T_TOK   32768
#define C_DIM   512
#define MLPD    2048
#define NWIN_T  512      // total windows (B * 64)
#define HEADS_N 16

// Scratch (device globals: allocation-free per harness rules)
__device__ float g_xw[(size_t)T_TOK * C_DIM];
__device__ float g_q [(size_t)T_TOK * C_DIM];
__device__ float g_k [(size_t)T_TOK * C_DIM];
__device__ float g_v [(size_t)T_TOK * C_DIM];
__device__ float g_ctx[(size_t)T_TOK * C_DIM];
__device__ float g_hid[(size_t)T_TOK * C_DIM];
__device__ float g_y [(size_t)T_TOK * C_DIM];
__device__ float g_h1[(size_t)T_TOK * MLPD];

// ---------------------------------------------------------------------------
// LayerNorm (+ optional shift+window permute of the SOURCE row).
// One block per output row t. 128 threads, float4 each.
// permute=1: t is a windowed index; source row = original-layout row.
// ---------------------------------------------------------------------------
__global__ void ln_kernel(const float* __restrict__ x,
                          const float* __restrict__ g,
                          const float* __restrict__ b,
                          float* __restrict__ out, int permute)
{
    int t = blockIdx.x;
    int src = t;
    if (permute) {
        int bb  = t >> 12;
        int win = (t >> 6) & 63;
        int n   = t & 63;
        int hs  = ((win >> 3) << 3) + (n >> 3);   // shifted-image coords
        int ws  = ((win & 7) << 3) + (n & 7);
        int h   = (hs + 4) & 63;                  // un-shift to original
        int w   = (ws + 4) & 63;
        src = (bb << 12) + (h << 6) + w;
    }
    int tid = threadIdx.x;                        // 128 threads
    float4 val = ((const float4*)(x + (size_t)src * C_DIM))[tid];
    float s  = val.x + val.y + val.z + val.w;
    float s2 = val.x*val.x + val.y*val.y + val.z*val.z + val.w*val.w;
    #pragma unroll
    for (int o = 16; o; o >>= 1) {
        s  += __shfl_xor_sync(0xffffffffu, s,  o);
        s2 += __shfl_xor_sync(0xffffffffu, s2, o);
    }
    __shared__ float sb[4], s2b[4];
    int warp = tid >> 5, lane = tid & 31;
    if (lane == 0) { sb[warp] = s; s2b[warp] = s2; }
    __syncthreads();
    s  = sb[0] + sb[1] + sb[2] + sb[3];
    s2 = s2b[0] + s2b[1] + s2b[2] + s2b[3];
    float mean = s * (1.0f / C_DIM);
    float var  = s2 * (1.0f / C_DIM) - mean * mean;
    float inv  = rsqrtf(var + 1e-5f);
    float4 gg = ((const float4*)g)[tid];
    float4 bb4 = ((const float4*)b)[tid];
    float4 o4;
    o4.x = (val.x - mean) * inv * gg.x + bb4.x;
    o4.y = (val.y - mean) * inv * gg.y + bb4.y;
    o4.z = (val.z - mean) * inv * gg.z + bb4.z;
    o4.w = (val.w - mean) * inv * gg.w + bb4.w;
    ((float4*)(out + (size_t)t * C_DIM))[tid] = o4;
}

// ---------------------------------------------------------------------------
// SGEMM  C[M,N] = epilogue( A[M,K] @ W[K,N] + bias ), 128x128x8 tile,
// 256 threads, 8x8 microtile. Epilogue modes:
//   0: C = (AW + bias) * alpha
//   1: window-reverse permute + residual: C[perm(row)] = res[perm(row)] + v
//   2: exact GELU
//   3: residual: C[row] = res[row] + v
// M, N, K all multiples of tile sizes (no bounds checks needed here).
// ---------------------------------------------------------------------------
#define BM 128
#define BN 128
#define BK 8
#define TM 8
#define TN 8

__global__ __launch_bounds__(256)
void sgemm_ep(const float* __restrict__ A, const float* __restrict__ W,
              const float* __restrict__ bias, const float* __restrict__ res,
              float* __restrict__ C, int M, int N, int K,
              float alpha, int mode)
{
    __shared__ float As[BK][BM];
    __shared__ float Bs[BK][BN];
    int tid = threadIdx.x;
    int bm0 = blockIdx.x * BM;
    int bn0 = blockIdx.y * BN;
    int tx = tid & 15, ty = tid >> 4;

    float acc[TM][TN];
    #pragma unroll
    for (int i = 0; i < TM; i++)
        #pragma unroll
        for (int j = 0; j < TN; j++) acc[i][j] = 0.0f;

    int aRow = tid >> 1;            // 0..127
    int aCol = (tid & 1) * 4;       // 0 or 4
    int bRow = tid >> 5;            // 0..7
    int bCol = (tid & 31) * 4;      // 0..124

    const float* Aptr = A + (size_t)(bm0 + aRow) * K + aCol;
    const float* Wbase = W + bn0 + bCol;

    for (int k0 = 0; k0 < K; k0 += BK) {
        float4 a = *(const float4*)(Aptr + k0);
        As[aCol + 0][aRow] = a.x;
        As[aCol + 1][aRow] = a.y;
        As[aCol + 2][aRow] = a.z;
        As[aCol + 3][aRow] = a.w;
        float4 bvec = *(const float4*)(Wbase + (size_t)(k0 + bRow) * N);
        *(float4*)&Bs[bRow][bCol] = bvec;
        __syncthreads();
        #pragma unroll
        for (int kk = 0; kk < BK; kk++) {
            float ra[TM], rb[TN];
            #pragma unroll
            for (int i = 0; i < TM; i++) ra[i] = As[kk][ty * TM + i];
            #pragma unroll
            for (int j = 0; j < TN; j++) rb[j] = Bs[kk][tx * TN + j];
            #pragma unroll
            for (int i = 0; i < TM; i++)
                #pragma unroll
                for (int j = 0; j < TN; j++)
                    acc[i][j] += ra[i] * rb[j];
        }
        __syncthreads();
    }

    #pragma unroll
    for (int i = 0; i < TM; i++) {
        int row = bm0 + ty * TM + i;
        int orow = row;
        if (mode == 1) {
            int bb  = row >> 12;
            int win = (row >> 6) & 63;
            int n   = row & 63;
            int hs  = ((win >> 3) << 3) + (n >> 3);
            int ws  = ((win & 7) << 3) + (n & 7);
            int h   = (hs + 4) & 63;
            int w   = (ws + 4) & 63;
            orow = (bb << 12) + (h << 6) + w;
        }
        #pragma unroll
        for (int j = 0; j < TN; j++) {
            int col = bn0 + tx * TN + j;
            float v = (acc[i][j] + bias[col]) * alpha;
            if (mode == 2) {
                v = 0.5f * v * (1.0f + erff(v * 0.70710678118654752f));
            } else if (mode == 1 || mode == 3) {
                v += res[(size_t)orow * N + col];
            }
            C[(size_t)orow * N + col] = v;
        }
    }
}

// ---------------------------------------------------------------------------
// Windowed attention: one block per (window, head). 256 threads.
// q already scaled by 1/sqrt(dh). Adds rel-pos bias and shift mask, softmax,
// then P @ V. All in shared memory (N=64, dh=32).
// ---------------------------------------------------------------------------
__global__ __launch_bounds__(256)
void attn_kernel(const float* __restrict__ q, const float* __restrict__ k,
                 const float* __restrict__ v,
                 const float* __restrict__ bias_table,
                 float* __restrict__ ctx)
{
    int blk = blockIdx.x;          // w * 16 + h
    int w = blk >> 4;
    int h = blk & 15;
    __shared__ float qs[64][32], ks[64][32], vs[64][32];
    __shared__ float sc[64][65];
    int tid = threadIdx.x;
    size_t base = (size_t)(w * 64) * C_DIM + h * 32;

    #pragma unroll
    for (int it = 0; it < 8; it++) {
        int e = tid + it * 256;
        int n = e >> 5, d = e & 31;
        size_t gidx = base + (size_t)n * C_DIM + d;
        qs[n][d] = q[gidx];
        ks[n][d] = k[gidx];
        vs[n][d] = v[gidx];
    }
    __syncthreads();

    int win = w & 63;
    int wh = win >> 3, ww = win & 7;

    #pragma unroll
    for (int it = 0; it < 16; it++) {
        int e = tid + it * 256;
        int n = e >> 6, m = e & 63;
        float s = 0.0f;
        #pragma unroll
        for (int d = 0; d < 32; d++) s += qs[n][d] * ks[m][d];
        int i1 = n >> 3, j1 = n & 7, i2 = m >> 3, j2 = m & 7;
        int rel = (i1 - i2 + 7) * 15 + (j1 - j2 + 7);
        s += bias_table[rel * HEADS_N + h];
        // shift-window mask via region ids (regions equal -> 0, else -100)
        int hs1 = wh * 8 + i1, ws1 = ww * 8 + j1;
        int hs2 = wh * 8 + i2, ws2 = ww * 8 + j2;
        int r1 = (hs1 < 56 ? 0 : (hs1 < 60 ? 1 : 2)) * 3 + (ws1 < 56 ? 0 : (ws1 < 60 ? 1 : 2));
        int r2 = (hs2 < 56 ? 0 : (hs2 < 60 ? 1 : 2)) * 3 + (ws2 < 56 ? 0 : (ws2 < 60 ? 1 : 2));
        if (r1 != r2) s -= 100.0f;
        sc[n][m] = s;
    }
    __syncthreads();

    // softmax: 8 warps x 8 rows each; each lane holds 2 columns
    int warp = tid >> 5, lane = tid & 31;
    #pragma unroll
    for (int rr = 0; rr < 8; rr++) {
        int n = warp * 8 + rr;
        float a = sc[n][lane], b = sc[n][lane + 32];
        float mx = fmaxf(a, b);
        #pragma unroll
        for (int o = 16; o; o >>= 1) mx = fmaxf(mx, __shfl_xor_sync(0xffffffffu, mx, o));
        float e1 = expf(a - mx), e2 = expf(b - mx);
        float sm = e1 + e2;
        #pragma unroll
        for (int o = 16; o; o >>= 1) sm += __shfl_xor_sync(0xffffffffu, sm, o);
        float inv = 1.0f / sm;
        sc[n][lane]      = e1 * inv;
        sc[n][lane + 32] = e2 * inv;
    }
    __syncthreads();

    #pragma unroll
    for (int it = 0; it < 8; it++) {
        int e = tid + it * 256;
        int n = e >> 5, d = e & 31;
        float s = 0.0f;
        #pragma unroll
        for (int m = 0; m < 64; m++) s += sc[n][m] * vs[m][d];
        ctx[base + (size_t)n * C_DIM + d] = s;
    }
}

// ---------------------------------------------------------------------------
// Launcher
// ---------------------------------------------------------------------------
extern "C" void kernel_launch(void* const* d_in, const int* in_sizes, int n_in,
                              void* d_out, int out_size)
{
    const float* x      = (const float*)d_in[0];
    const float* ln1_g  = (const float*)d_in[1];
    const float* ln1_b  = (const float*)d_in[2];
    const float* wq     = (const float*)d_in[3];
    const float* bq     = (const float*)d_in[4];
    const float* wk     = (const float*)d_in[5];
    const float* bk     = (const float*)d_in[6];
    const float* wv     = (const float*)d_in[7];
    const float* bv     = (const float*)d_in[8];
    const float* relt   = (const float*)d_in[9];
    const float* wo     = (const float*)d_in[10];
    const float* bo     = (const float*)d_in[11];
    const float* ln2_g  = (const float*)d_in[12];
    const float* ln2_b  = (const float*)d_in[13];
    const float* w1     = (const float*)d_in[14];
    const float* b1     = (const float*)d_in[15];
    const float* w2     = (const float*)d_in[16];
    const float* b2     = (const float*)d_in[17];
    float* out          = (float*)d_out;

    float *p_xw, *p_q, *p_k, *p_v, *p_ctx, *p_hid, *p_y, *p_h1;
    cudaGetSymbolAddress((void**)&p_xw,  g_xw);
    cudaGetSymbolAddress((void**)&p_q,   g_q);
    cudaGetSymbolAddress((void**)&p_k,   g_k);
    cudaGetSymbolAddress((void**)&p_v,   g_v);
    cudaGetSymbolAddress((void**)&p_ctx, g_ctx);
    cudaGetSymbolAddress((void**)&p_hid, g_hid);
    cudaGetSymbolAddress((void**)&p_y,   g_y);
    cudaGetSymbolAddress((void**)&p_h1,  g_h1);

    const float qscale = 0.17677669529663689f;  // 1/sqrt(32)

    // 1. LN1 + cyclic shift + window partition -> xw
    ln_kernel<<<T_TOK, 128>>>(x, ln1_g, ln1_b, p_xw, 1);

    // 2. Q,K,V projections (Q folded with 1/sqrt(dh))
    dim3 g4(T_TOK / BM, C_DIM / BN);
    sgemm_ep<<<g4, 256>>>(p_xw, wq, bq, nullptr, p_q, T_TOK, C_DIM, C_DIM, qscale, 0);
    sgemm_ep<<<g4, 256>>>(p_xw, wk, bk, nullptr, p_k, T_TOK, C_DIM, C_DIM, 1.0f, 0);
    sgemm_ep<<<g4, 256>>>(p_xw, wv, bv, nullptr, p_v, T_TOK, C_DIM, C_DIM, 1.0f, 0);

    // 3. Windowed attention with bias + shift mask
    attn_kernel<<<NWIN_T * HEADS_N, 256>>>(p_q, p_k, p_v, relt, p_ctx);

    // 4. Output projection + window reverse + un-shift + residual -> hidden
    sgemm_ep<<<g4, 256>>>(p_ctx, wo, bo, x, p_hid, T_TOK, C_DIM, C_DIM, 1.0f, 1);

    // 5. LN2
    ln_kernel<<<T_TOK, 128>>>(p_hid, ln2_g, ln2_b, p_y, 0);

    // 6. MLP fc1 + exact GELU
    dim3 g16(T_TOK / BM, MLPD / BN);
    sgemm_ep<<<g16, 256>>>(p_y, w1, b1, nullptr, p_h1, T_TOK, MLPD, C_DIM, 1.0f, 2);

    // 7. MLP fc2 + residual -> output
    sgemm_ep<<<g4, 256>>>(p_h1, w2, b2, p_hid, out, T_TOK, C_DIM, MLPD, 1.0f, 3);
}

// round 4
// speedup vs baseline: 5.1235x; 5.1235x over previous
#include <cuda_runtime.h>
#include <cuda_bf16.h>
#include <cstdint>

// ---------------------------------------------------------------------------
// Swin block on GB300 (sm_103 plain target): bf16 mma.sync GEMMs + cp.async
// pipeline; fp32 attention/LN/residual spine.
// B=8, H=W=64, C=512, HEADS=16, dh=32, WS=8, SHIFT=4, N=64, T=32768, MLP=2048.
// ---------------------------------------------------------------------------

#define T_TOK   32768
#define C_DIM   512
#define MLPD    2048
#define HEADS_N 16

// ------------------------------- scratch -----------------------------------
__device__ float g_q  [(size_t)T_TOK * C_DIM];
__device__ float g_k  [(size_t)T_TOK * C_DIM];
__device__ float g_v  [(size_t)T_TOK * C_DIM];
__device__ float g_hid[(size_t)T_TOK * C_DIM];
__device__ __nv_bfloat16 b_xw [(size_t)T_TOK * C_DIM];
__device__ __nv_bfloat16 b_ctx[(size_t)T_TOK * C_DIM];
__device__ __nv_bfloat16 b_y  [(size_t)T_TOK * C_DIM];
__device__ __nv_bfloat16 b_h1 [(size_t)T_TOK * MLPD];
__device__ __nv_bfloat16 b_wqT[(size_t)C_DIM * C_DIM];
__device__ __nv_bfloat16 b_wkT[(size_t)C_DIM * C_DIM];
__device__ __nv_bfloat16 b_wvT[(size_t)C_DIM * C_DIM];
__device__ __nv_bfloat16 b_woT[(size_t)C_DIM * C_DIM];
__device__ __nv_bfloat16 b_w1T[(size_t)MLPD * C_DIM];
__device__ __nv_bfloat16 b_w2T[(size_t)C_DIM * MLPD];

// ------------------------------- helpers -----------------------------------
__device__ __forceinline__ uint32_t smem_u32(const void* p) {
    uint32_t a;
    asm("{ .reg .u64 t; cvta.to.shared.u64 t, %1; cvt.u32.u64 %0, t; }"
        : "=r"(a) : "l"(p));
    return a;
}
__device__ __forceinline__ void cp_async16(uint32_t dst, const void* src) {
    asm volatile("cp.async.cg.shared.global [%0], [%1], 16;" :: "r"(dst), "l"(src));
}
__device__ __forceinline__ void cp_commit() { asm volatile("cp.async.commit_group;"); }
__device__ __forceinline__ void cp_wait2()  { asm volatile("cp.async.wait_group 2;" ::: "memory"); }

__device__ __forceinline__ void ldm_x4(uint32_t* r, uint32_t addr) {
    asm volatile("ldmatrix.sync.aligned.m8n8.x4.shared.b16 {%0,%1,%2,%3}, [%4];"
                 : "=r"(r[0]), "=r"(r[1]), "=r"(r[2]), "=r"(r[3]) : "r"(addr));
}
__device__ __forceinline__ void mma_bf16(float* c, const uint32_t* a, const uint32_t* b) {
    asm volatile("mma.sync.aligned.m16n8k16.row.col.f32.bf16.bf16.f32 "
                 "{%0,%1,%2,%3}, {%4,%5,%6,%7}, {%8,%9}, {%0,%1,%2,%3};"
                 : "+f"(c[0]), "+f"(c[1]), "+f"(c[2]), "+f"(c[3])
                 : "r"(a[0]), "r"(a[1]), "r"(a[2]), "r"(a[3]), "r"(b[0]), "r"(b[1]));
}

// -------------------- weight transpose + fp32->bf16 ------------------------
// Wt[n*K + k] = bf16( W[k*N + n] )
__global__ void transp_kernel(const float* __restrict__ W, __nv_bfloat16* __restrict__ Wt,
                              int K, int N)
{
    __shared__ float t[32][33];
    int n0 = blockIdx.x * 32, k0 = blockIdx.y * 32;
    int x = threadIdx.x, y = threadIdx.y;   // 32 x 8
    #pragma unroll
    for (int i = 0; i < 32; i += 8)
        t[y + i][x] = W[(size_t)(k0 + y + i) * N + n0 + x];
    __syncthreads();
    #pragma unroll
    for (int i = 0; i < 32; i += 8)
        Wt[(size_t)(n0 + y + i) * K + k0 + x] = __float2bfloat16(t[x][y + i]);
}

// ----------------------- LayerNorm (+permute), bf16 out --------------------
__global__ void ln_kernel(const float* __restrict__ x,
                          const float* __restrict__ g,
                          const float* __restrict__ b,
                          __nv_bfloat16* __restrict__ out, int permute)
{
    int t = blockIdx.x;
    int src = t;
    if (permute) {
        int bb  = t >> 12;
        int win = (t >> 6) & 63;
        int n   = t & 63;
        int hs  = ((win >> 3) << 3) + (n >> 3);
        int ws  = ((win & 7) << 3) + (n & 7);
        int h   = (hs + 4) & 63;
        int w   = (ws + 4) & 63;
        src = (bb << 12) + (h << 6) + w;
    }
    int tid = threadIdx.x;  // 128
    float4 val = ((const float4*)(x + (size_t)src * C_DIM))[tid];
    float s  = val.x + val.y + val.z + val.w;
    float s2 = val.x*val.x + val.y*val.y + val.z*val.z + val.w*val.w;
    #pragma unroll
    for (int o = 16; o; o >>= 1) {
        s  += __shfl_xor_sync(0xffffffffu, s,  o);
        s2 += __shfl_xor_sync(0xffffffffu, s2, o);
    }
    __shared__ float sb[4], s2b[4];
    int warp = tid >> 5, lane = tid & 31;
    if (lane == 0) { sb[warp] = s; s2b[warp] = s2; }
    __syncthreads();
    s  = sb[0] + sb[1] + sb[2] + sb[3];
    s2 = s2b[0] + s2b[1] + s2b[2] + s2b[3];
    float mean = s * (1.0f / C_DIM);
    float var  = s2 * (1.0f / C_DIM) - mean * mean;
    float inv  = rsqrtf(var + 1e-5f);
    float4 gg  = ((const float4*)g)[tid];
    float4 bb4 = ((const float4*)b)[tid];
    float o0 = (val.x - mean) * inv * gg.x + bb4.x;
    float o1 = (val.y - mean) * inv * gg.y + bb4.y;
    float o2 = (val.z - mean) * inv * gg.z + bb4.z;
    float o3 = (val.w - mean) * inv * gg.w + bb4.w;
    __nv_bfloat162 p0, p1;
    p0.x = __float2bfloat16(o0); p0.y = __float2bfloat16(o1);
    p1.x = __float2bfloat16(o2); p1.y = __float2bfloat16(o3);
    __nv_bfloat162* op = (__nv_bfloat162*)(out + (size_t)t * C_DIM) + 2 * tid;
    op[0] = p0; op[1] = p1;
}

// ------------------------- bf16 mma.sync GEMM ------------------------------
// C[M, Nt] = epi( A[M,K]bf16 @ Bt[Nt,K]bf16^T + bias )
// mode 0: fp32, *alpha   mode 1: fp32, permuted row + res
// mode 2: bf16, GELU     mode 3: fp32, + res
//
// CTA tile 128x128, k-chunk 32, 4-stage cp.async pipeline.
// 8 warps: warp_m = wid&1 (M 64), warp_n = wid>>1 (N 32).
// Smem per stage: A 128 rows x 80B, B 128 rows x 80B (64B data + 16B pad).

#define STAGES 4
#define ROWB   80                       // bytes per smem row (64 data + 16 pad)
#define STG_B  (2 * 128 * ROWB)         // 20480 per stage
#define SMEM_TOT (STAGES * STG_B)       // 81920

__global__ __launch_bounds__(256, 2)
void gemm_tc(const __nv_bfloat16* __restrict__ A, const __nv_bfloat16* __restrict__ Bt,
             const float* __restrict__ bias, const float* __restrict__ res,
             void* __restrict__ outp, int K, int Nt, float alpha, int mode)
{
    extern __shared__ char smem[];
    const uint32_t su = smem_u32(smem);
    const int tid = threadIdx.x, wid = tid >> 5, lane = tid & 31;
    const int m0 = blockIdx.x * 128, n0 = blockIdx.y * 128;
    const int wm0 = (wid & 1) * 64, wn0 = (wid >> 1) * 32;

    // global load slots: 2 chunks of 16B for A, 2 for B
    const char* aG[2]; const char* bG[2];
    uint32_t aS[2], bS[2];
    #pragma unroll
    for (int j = 0; j < 2; j++) {
        int idx = tid + j * 256;            // 0..511
        int r = idx >> 2, c = idx & 3;      // row 0..127, 16B chunk 0..3
        aG[j] = (const char*)(A  + (size_t)(m0 + r) * K + c * 8);
        bG[j] = (const char*)(Bt + (size_t)(n0 + r) * K + c * 8);
        aS[j] = su + r * ROWB + c * 16;
        bS[j] = su + 128 * ROWB + r * ROWB + c * 16;
    }

    const int NC = K >> 5;                  // k-chunks of 32

    // prologue: stages 0..2 hold chunks 0..2
    #pragma unroll
    for (int s = 0; s < STAGES - 1; s++) {
        int koff = s * 64;                  // bytes (32 bf16)
        #pragma unroll
        for (int j = 0; j < 2; j++) {
            cp_async16(aS[j] + s * STG_B, aG[j] + koff);
            cp_async16(bS[j] + s * STG_B, bG[j] + koff);
        }
        cp_commit();
    }

    float acc[4][4][4];
    #pragma unroll
    for (int mt = 0; mt < 4; mt++)
        #pragma unroll
        for (int nt = 0; nt < 4; nt++)
            #pragma unroll
            for (int i = 0; i < 4; i++) acc[mt][nt][i] = 0.0f;

    // ldmatrix base addresses (per-lane)
    // A x4: matrices {rows0-7,k0}{rows8-15,k0}{rows0-7,k8}{rows8-15,k8}
    uint32_t aRow = (lane & 7) + ((lane >> 3) & 1) * 8;
    uint32_t aKof = (lane >> 4) * 16;       // bytes (8 elems)
    uint32_t aBase = su + (wm0 + aRow) * ROWB + aKof;
    // B x4: matrices {n0-7,k0}{n0-7,k8}{n8-15,k0}{n8-15,k8}
    uint32_t bRow = (lane & 7) + ((lane >> 4)) * 8;
    uint32_t bKof = ((lane >> 3) & 1) * 16;
    uint32_t bBase = su + 128 * ROWB + (wn0 + bRow) * ROWB + bKof;

    for (int ch = 0; ch < NC; ch++) {
        int cur = ch & (STAGES - 1);                       // stage holding chunk ch
        int wst = (ch + STAGES - 1) & (STAGES - 1);        // stage to write chunk ch+3
        cp_wait2();
        __syncthreads();

        uint32_t aStage = aBase + cur * STG_B;
        uint32_t bStage = bBase + cur * STG_B;
        #pragma unroll
        for (int k16 = 0; k16 < 2; k16++) {
            uint32_t bf[2][4];
            ldm_x4(bf[0], bStage + k16 * 32);
            ldm_x4(bf[1], bStage + 16 * ROWB + k16 * 32);
            #pragma unroll
            for (int mt = 0; mt < 4; mt++) {
                uint32_t af[4];
                ldm_x4(af, aStage + mt * 16 * ROWB + k16 * 32);
                #pragma unroll
                for (int nt = 0; nt < 4; nt++)
                    mma_bf16(acc[mt][nt], af, &bf[nt >> 1][(nt & 1) * 2]);
            }
        }
        __syncthreads();

        int nx = ch + STAGES - 1;
        if (nx < NC) {
            int koff = nx * 64;
            #pragma unroll
            for (int j = 0; j < 2; j++) {
                cp_async16(aS[j] + wst * STG_B, aG[j] + koff);
                cp_async16(bS[j] + wst * STG_B, bG[j] + koff);
            }
        }
        cp_commit();   // commit every iter (possibly empty) to keep counts aligned
    }

    // ---------------- epilogue ----------------
    // thread in frag: rows r_lo = lane>>2, r_hi = r_lo+8; cols (lane&3)*2, +1
    int rl = lane >> 2, c2 = (lane & 3) * 2;
    #pragma unroll
    for (int mt = 0; mt < 4; mt++) {
        int rows[2] = { m0 + wm0 + mt * 16 + rl, m0 + wm0 + mt * 16 + rl + 8 };
        int orows[2] = { rows[0], rows[1] };
        if (mode == 1) {
            #pragma unroll
            for (int h = 0; h < 2; h++) {
                int row = rows[h];
                int bb  = row >> 12;
                int win = (row >> 6) & 63;
                int n   = row & 63;
                int hs  = ((win >> 3) << 3) + (n >> 3);
                int ws  = ((win & 7) << 3) + (n & 7);
                int hh  = (hs + 4) & 63;
                int ww  = (ws + 4) & 63;
                orows[h] = (bb << 12) + (hh << 6) + ww;
            }
        }
        #pragma unroll
        for (int nt = 0; nt < 4; nt++) {
            int col = n0 + wn0 + nt * 8 + c2;
            float bia0 = bias[col], bia1 = bias[col + 1];
            #pragma unroll
            for (int h = 0; h < 2; h++) {
                float v0 = (acc[mt][nt][h * 2]     + bia0) * alpha;
                float v1 = (acc[mt][nt][h * 2 + 1] + bia1) * alpha;
                size_t rb = (size_t)orows[h] * Nt + col;
                if (mode == 2) {
                    v0 = 0.5f * v0 * (1.0f + erff(v0 * 0.70710678118654752f));
                    v1 = 0.5f * v1 * (1.0f + erff(v1 * 0.70710678118654752f));
                    __nv_bfloat162 p;
                    p.x = __float2bfloat16(v0); p.y = __float2bfloat16(v1);
                    *(__nv_bfloat162*)((__nv_bfloat16*)outp + rb) = p;
                } else {
                    if (mode == 1 || mode == 3) {
                        float2 r2 = *(const float2*)(res + rb);
                        v0 += r2.x; v1 += r2.y;
                    }
                    float2 o2; o2.x = v0; o2.y = v1;
                    *(float2*)((float*)outp + rb) = o2;
                }
            }
        }
    }
}

// ------------------------- windowed attention (fp32) -----------------------
__global__ __launch_bounds__(256)
void attn_kernel(const float* __restrict__ q, const float* __restrict__ k,
                 const float* __restrict__ v,
                 const float* __restrict__ bias_table,
                 __nv_bfloat16* __restrict__ ctx)
{
    int blk = blockIdx.x;
    int w = blk >> 4;
    int h = blk & 15;
    __shared__ float qs[64][33], ks[64][33], vs[64][33];
    __shared__ float sc[64][65];
    int tid = threadIdx.x;
    size_t base = (size_t)(w * 64) * C_DIM + h * 32;

    #pragma unroll
    for (int it = 0; it < 8; it++) {
        int e = tid + it * 256;
        int n = e >> 5, d = e & 31;
        size_t gidx = base + (size_t)n * C_DIM + d;
        qs[n][d] = q[gidx];
        ks[n][d] = k[gidx];
        vs[n][d] = v[gidx];
    }
    __syncthreads();

    int win = w & 63;
    int wh = win >> 3, ww = win & 7;

    #pragma unroll
    for (int it = 0; it < 16; it++) {
        int e = tid + it * 256;
        int n = e >> 6, m = e & 63;
        float s = 0.0f;
        #pragma unroll
        for (int d = 0; d < 32; d++) s += qs[n][d] * ks[m][d];
        int i1 = n >> 3, j1 = n & 7, i2 = m >> 3, j2 = m & 7;
        int rel = (i1 - i2 + 7) * 15 + (j1 - j2 + 7);
        s += bias_table[rel * HEADS_N + h];
        int hs1 = wh * 8 + i1, ws1 = ww * 8 + j1;
        int hs2 = wh * 8 + i2, ws2 = ww * 8 + j2;
        int r1 = (hs1 < 56 ? 0 : (hs1 < 60 ? 1 : 2)) * 3 + (ws1 < 56 ? 0 : (ws1 < 60 ? 1 : 2));
        int r2 = (hs2 < 56 ? 0 : (hs2 < 60 ? 1 : 2)) * 3 + (ws2 < 56 ? 0 : (ws2 < 60 ? 1 : 2));
        if (r1 != r2) s -= 100.0f;
        sc[n][m] = s;
    }
    __syncthreads();

    int warp = tid >> 5, lane = tid & 31;
    #pragma unroll
    for (int rr = 0; rr < 8; rr++) {
        int n = warp * 8 + rr;
        float a = sc[n][lane], b = sc[n][lane + 32];
        float mx = fmaxf(a, b);
        #pragma unroll
        for (int o = 16; o; o >>= 1) mx = fmaxf(mx, __shfl_xor_sync(0xffffffffu, mx, o));
        float e1 = expf(a - mx), e2 = expf(b - mx);
        float sm = e1 + e2;
        #pragma unroll
        for (int o = 16; o; o >>= 1) sm += __shfl_xor_sync(0xffffffffu, sm, o);
        float inv = 1.0f / sm;
        sc[n][lane]      = e1 * inv;
        sc[n][lane + 32] = e2 * inv;
    }
    __syncthreads();

    #pragma unroll
    for (int it = 0; it < 8; it++) {
        int e = tid + it * 256;
        int n = e >> 5, d = e & 31;
        float s = 0.0f;
        #pragma unroll
        for (int m = 0; m < 64; m++) s += sc[n][m] * vs[m][d];
        ctx[base + (size_t)n * C_DIM + d] = __float2bfloat16(s);
    }
}

// ------------------------------- launcher ----------------------------------
extern "C" void kernel_launch(void* const* d_in, const int* in_sizes, int n_in,
                              void* d_out, int out_size)
{
    const float* x      = (const float*)d_in[0];
    const float* ln1_g  = (const float*)d_in[1];
    const float* ln1_b  = (const float*)d_in[2];
    const float* wq     = (const float*)d_in[3];
    const float* bq     = (const float*)d_in[4];
    const float* wk     = (const float*)d_in[5];
    const float* bk     = (const float*)d_in[6];
    const float* wv     = (const float*)d_in[7];
    const float* bv     = (const float*)d_in[8];
    const float* relt   = (const float*)d_in[9];
    const float* wo     = (const float*)d_in[10];
    const float* bo     = (const float*)d_in[11];
    const float* ln2_g  = (const float*)d_in[12];
    const float* ln2_b  = (const float*)d_in[13];
    const float* w1     = (const float*)d_in[14];
    const float* b1     = (const float*)d_in[15];
    const float* w2     = (const float*)d_in[16];
    const float* b2     = (const float*)d_in[17];
    float* out          = (float*)d_out;

    float *p_q, *p_k, *p_v, *p_hid;
    __nv_bfloat16 *p_xw, *p_ctx, *p_y, *p_h1;
    __nv_bfloat16 *p_wqT, *p_wkT, *p_wvT, *p_woT, *p_w1T, *p_w2T;
    cudaGetSymbolAddress((void**)&p_q,   g_q);
    cudaGetSymbolAddress((void**)&p_k,   g_k);
    cudaGetSymbolAddress((void**)&p_v,   g_v);
    cudaGetSymbolAddress((void**)&p_hid, g_hid);
    cudaGetSymbolAddress((void**)&p_xw,  b_xw);
    cudaGetSymbolAddress((void**)&p_ctx, b_ctx);
    cudaGetSymbolAddress((void**)&p_y,   b_y);
    cudaGetSymbolAddress((void**)&p_h1,  b_h1);
    cudaGetSymbolAddress((void**)&p_wqT, b_wqT);
    cudaGetSymbolAddress((void**)&p_wkT, b_wkT);
    cudaGetSymbolAddress((void**)&p_wvT, b_wvT);
    cudaGetSymbolAddress((void**)&p_woT, b_woT);
    cudaGetSymbolAddress((void**)&p_w1T, b_w1T);
    cudaGetSymbolAddress((void**)&p_w2T, b_w2T);

    cudaFuncSetAttribute(gemm_tc, cudaFuncAttributeMaxDynamicSharedMemorySize, SMEM_TOT);

    const float qscale = 0.17677669529663689f;  // 1/sqrt(32)

    // 0. weight transpose + bf16 convert
    dim3 tb(32, 8);
    transp_kernel<<<dim3(C_DIM / 32, C_DIM / 32), tb>>>(wq, p_wqT, C_DIM, C_DIM);
    transp_kernel<<<dim3(C_DIM / 32, C_DIM / 32), tb>>>(wk, p_wkT, C_DIM, C_DIM);
    transp_kernel<<<dim3(C_DIM / 32, C_DIM / 32), tb>>>(wv, p_wvT, C_DIM, C_DIM);
    transp_kernel<<<dim3(C_DIM / 32, C_DIM / 32), tb>>>(wo, p_woT, C_DIM, C_DIM);
    transp_kernel<<<dim3(MLPD / 32, C_DIM / 32), tb>>>(w1, p_w1T, C_DIM, MLPD);
    transp_kernel<<<dim3(C_DIM / 32, MLPD / 32), tb>>>(w2, p_w2T, MLPD, C_DIM);

    // 1. LN1 + shift + window partition (bf16)
    ln_kernel<<<T_TOK, 128>>>(x, ln1_g, ln1_b, p_xw, 1);

    // 2. QKV projections (tensor cores), fp32 out for attention
    dim3 g4(T_TOK / 128, C_DIM / 128);
    gemm_tc<<<g4, 256, SMEM_TOT>>>(p_xw, p_wqT, bq, nullptr, p_q, C_DIM, C_DIM, qscale, 0);
    gemm_tc<<<g4, 256, SMEM_TOT>>>(p_xw, p_wkT, bk, nullptr, p_k, C_DIM, C_DIM, 1.0f, 0);
    gemm_tc<<<g4, 256, SMEM_TOT>>>(p_xw, p_wvT, bv, nullptr, p_v, C_DIM, C_DIM, 1.0f, 0);

    // 3. windowed attention (fp32 math, bf16 ctx out)
    attn_kernel<<<512 * HEADS_N, 256>>>(p_q, p_k, p_v, relt, p_ctx);

    // 4. output proj + window reverse + residual
    gemm_tc<<<g4, 256, SMEM_TOT>>>(p_ctx, p_woT, bo, x, p_hid, C_DIM, C_DIM, 1.0f, 1);

    // 5. LN2 (bf16 out)
    ln_kernel<<<T_TOK, 128>>>(p_hid, ln2_g, ln2_b, p_y, 0);

    // 6. MLP fc1 + GELU (bf16 out)
    dim3 g16(T_TOK / 128, MLPD / 128);
    gemm_tc<<<g16, 256, SMEM_TOT>>>(p_y, p_w1T, b1, nullptr, p_h1, C_DIM, MLPD, 1.0f, 2);

    // 7. MLP fc2 + residual -> out
    gemm_tc<<<g4, 256, SMEM_TOT>>>(p_h1, p_w2T, b2, p_hid, out, MLPD, C_DIM, 1.0f, 3);
}